// round 1
// baseline (speedup 1.0000x reference)
#include <cuda_runtime.h>
#include <cuda_bf16.h>
#include <math.h>

// Problem constants
#define TOKENS   32768      // 16 * 2048
#define DIM      1024
#define HEADS    8
#define DHEAD    128
#define LN_EPS   1e-5f

// ---------------------------------------------------------------------------
// Scratch (device globals; cudaMalloc is forbidden)
// ---------------------------------------------------------------------------
__device__ float g_qn[TOKENS * DIM];          // layernormed q
__device__ float g_kvn[TOKENS * DIM];         // layernormed kv
__device__ float g_query[TOKENS * DIM];       // q projection
__device__ float g_kvproj[TOKENS * 2 * DIM];  // k|v projection
__device__ float g_ctx[TOKENS * DIM];         // attention context

// ---------------------------------------------------------------------------
// LayerNorm: one block per row of 1024, 256 threads, float4 per thread
// ---------------------------------------------------------------------------
__global__ void ln_kernel(const float* __restrict__ x,
                          const float* __restrict__ gamma,
                          const float* __restrict__ beta,
                          float* __restrict__ y) {
    const int row = blockIdx.x;
    const int tid = threadIdx.x;          // 0..255
    const float4* xr = (const float4*)(x + (size_t)row * DIM);
    float4 v = xr[tid];

    float s  = v.x + v.y + v.z + v.w;
    float sq = v.x * v.x + v.y * v.y + v.z * v.z + v.w * v.w;

    // warp reduce
    #pragma unroll
    for (int o = 16; o > 0; o >>= 1) {
        s  += __shfl_xor_sync(0xffffffffu, s,  o);
        sq += __shfl_xor_sync(0xffffffffu, sq, o);
    }
    __shared__ float rs[8], rq[8];
    const int wid = tid >> 5, lane = tid & 31;
    if (lane == 0) { rs[wid] = s; rq[wid] = sq; }
    __syncthreads();
    float tot = 0.f, totq = 0.f;
    #pragma unroll
    for (int i = 0; i < 8; i++) { tot += rs[i]; totq += rq[i]; }

    const float mu   = tot * (1.0f / DIM);
    const float var  = totq * (1.0f / DIM) - mu * mu;
    const float rinv = rsqrtf(var + LN_EPS);

    float4 g = ((const float4*)gamma)[tid];
    float4 b = ((const float4*)beta)[tid];
    float4 o;
    o.x = (v.x - mu) * rinv * g.x + b.x;
    o.y = (v.y - mu) * rinv * g.y + b.y;
    o.z = (v.z - mu) * rinv * g.z + b.z;
    o.w = (v.w - mu) * rinv * g.w + b.w;
    ((float4*)(y + (size_t)row * DIM))[tid] = o;
}

// ---------------------------------------------------------------------------
// SGEMM (TN): C[M,N] = A[M,K] * B[N,K]^T     (A, B row-major, K contiguous)
// Block tile 128x128, K-tile 16, 256 threads, 8x8 per thread.
// ---------------------------------------------------------------------------
#define BM 128
#define BN 128
#define BK 16
#define TM 8
#define TN 8

__global__ __launch_bounds__(256, 2)
void sgemm_tn(const float* __restrict__ A, const float* __restrict__ B,
              float* __restrict__ C, int M, int N, int K) {
    __shared__ float As[BK][BM];
    __shared__ float Bs[BK][BN];

    const int bm = blockIdx.y * BM;
    const int bn = blockIdx.x * BN;
    const int tid = threadIdx.x;              // 0..255
    const int ty = tid >> 4;                  // 0..15
    const int tx = tid & 15;                  // 0..15

    float acc[TM][TN];
    #pragma unroll
    for (int i = 0; i < TM; i++)
        #pragma unroll
        for (int j = 0; j < TN; j++) acc[i][j] = 0.f;

    for (int k0 = 0; k0 < K; k0 += BK) {
        // load A,B tiles: 128 rows x 16 k = 512 float4 each; 2 per thread
        #pragma unroll
        for (int i = 0; i < 2; i++) {
            const int idx = tid + i * 256;
            const int row = idx >> 2;          // 0..127
            const int k4  = (idx & 3) << 2;    // 0,4,8,12
            float4 va = *(const float4*)(A + (size_t)(bm + row) * K + k0 + k4);
            As[k4 + 0][row] = va.x; As[k4 + 1][row] = va.y;
            As[k4 + 2][row] = va.z; As[k4 + 3][row] = va.w;
            float4 vb = *(const float4*)(B + (size_t)(bn + row) * K + k0 + k4);
            Bs[k4 + 0][row] = vb.x; Bs[k4 + 1][row] = vb.y;
            Bs[k4 + 2][row] = vb.z; Bs[k4 + 3][row] = vb.w;
        }
        __syncthreads();

        #pragma unroll
        for (int k = 0; k < BK; k++) {
            float a[TM], b[TN];
            float4 a0 = *(const float4*)&As[k][ty * TM];
            float4 a1 = *(const float4*)&As[k][ty * TM + 4];
            a[0]=a0.x; a[1]=a0.y; a[2]=a0.z; a[3]=a0.w;
            a[4]=a1.x; a[5]=a1.y; a[6]=a1.z; a[7]=a1.w;
            float4 b0 = *(const float4*)&Bs[k][tx * TN];
            float4 b1 = *(const float4*)&Bs[k][tx * TN + 4];
            b[0]=b0.x; b[1]=b0.y; b[2]=b0.z; b[3]=b0.w;
            b[4]=b1.x; b[5]=b1.y; b[6]=b1.z; b[7]=b1.w;
            #pragma unroll
            for (int i = 0; i < TM; i++)
                #pragma unroll
                for (int j = 0; j < TN; j++)
                    acc[i][j] += a[i] * b[j];
        }
        __syncthreads();
    }

    #pragma unroll
    for (int i = 0; i < TM; i++) {
        float* crow = C + (size_t)(bm + ty * TM + i) * N + bn + tx * TN;
        #pragma unroll
        for (int j = 0; j < TN; j += 4) {
            float4 v = make_float4(acc[i][j], acc[i][j+1], acc[i][j+2], acc[i][j+3]);
            *(float4*)(crow + j) = v;
        }
    }
}

// ---------------------------------------------------------------------------
// Per-token attention over the HEADS axis: scores [8,8], softmax, context.
// One block (128 threads) per token.
// ---------------------------------------------------------------------------
__global__ __launch_bounds__(128)
void attn_kernel(const float* __restrict__ query,
                 const float* __restrict__ kvproj,
                 float* __restrict__ context) {
    const int t = blockIdx.x;
    const int tid = threadIdx.x;              // 0..127
    __shared__ float qs[DIM], ks[DIM], vs[DIM];
    __shared__ float w[HEADS * HEADS];

    const float4* qp = (const float4*)(query + (size_t)t * DIM);
    const float4* kp = (const float4*)(kvproj + (size_t)t * 2 * DIM);
    const float4* vp = kp + DIM / 4;
    ((float4*)qs)[tid]       = qp[tid];
    ((float4*)qs)[tid + 128] = qp[tid + 128];
    ((float4*)ks)[tid]       = kp[tid];
    ((float4*)ks)[tid + 128] = kp[tid + 128];
    ((float4*)vs)[tid]       = vp[tid];
    ((float4*)vs)[tid + 128] = vp[tid + 128];
    __syncthreads();

    __shared__ float sc[HEADS * HEADS];
    if (tid < HEADS * HEADS) {
        const int h = tid >> 3, g = tid & 7;
        const float* qq = qs + h * DHEAD;
        const float* kk = ks + g * DHEAD;
        float s = 0.f;
        #pragma unroll 8
        for (int d = 0; d < DHEAD; d++) s += qq[d] * kk[d];
        sc[tid] = s * 0.08838834764831845f;   // 1/sqrt(128)
    }
    __syncthreads();

    if (tid < HEADS) {
        float m = -1e30f;
        #pragma unroll
        for (int g = 0; g < HEADS; g++) m = fmaxf(m, sc[tid * 8 + g]);
        float e[HEADS], sum = 0.f;
        #pragma unroll
        for (int g = 0; g < HEADS; g++) { e[g] = expf(sc[tid * 8 + g] - m); sum += e[g]; }
        const float inv = 1.0f / sum;
        #pragma unroll
        for (int g = 0; g < HEADS; g++) w[tid * 8 + g] = e[g] * inv;
    }
    __syncthreads();

    // context[h, d] = sum_g w[h,g] * v[g,d]; tid = d (0..127)
    #pragma unroll
    for (int h = 0; h < HEADS; h++) {
        float a = 0.f;
        #pragma unroll
        for (int g = 0; g < HEADS; g++) a += w[h * 8 + g] * vs[g * DHEAD + tid];
        context[(size_t)t * DIM + h * DHEAD + tid] = a;
    }
}

// ---------------------------------------------------------------------------
// Launch
// ---------------------------------------------------------------------------
extern "C" void kernel_launch(void* const* d_in, const int* in_sizes, int n_in,
                              void* d_out, int out_size) {
    const float* q       = (const float*)d_in[0];
    const float* kv      = (const float*)d_in[1];
    const float* gamma_m = (const float*)d_in[2];
    const float* beta_m  = (const float*)d_in[3];
    const float* gamma_l = (const float*)d_in[4];
    const float* beta_l  = (const float*)d_in[5];
    const float* Wq      = (const float*)d_in[6];
    const float* Wkv     = (const float*)d_in[7];
    const float* Wo      = (const float*)d_in[8];
    float* out = (float*)d_out;

    float *qn, *kvn, *query, *kvproj, *ctx;
    cudaGetSymbolAddress((void**)&qn,     g_qn);
    cudaGetSymbolAddress((void**)&kvn,    g_kvn);
    cudaGetSymbolAddress((void**)&query,  g_query);
    cudaGetSymbolAddress((void**)&kvproj, g_kvproj);
    cudaGetSymbolAddress((void**)&ctx,    g_ctx);

    ln_kernel<<<TOKENS, 256>>>(q,  gamma_m, beta_m, qn);
    ln_kernel<<<TOKENS, 256>>>(kv, gamma_l, beta_l, kvn);

    // query = qn @ Wq^T          [32768,1024] x [1024,1024]^T
    sgemm_tn<<<dim3(DIM / BN, TOKENS / BM), 256>>>(qn, Wq, query, TOKENS, DIM, DIM);
    // kvproj = kvn @ Wkv^T       [32768,1024] x [2048,1024]^T
    sgemm_tn<<<dim3(2 * DIM / BN, TOKENS / BM), 256>>>(kvn, Wkv, kvproj, TOKENS, 2 * DIM, DIM);

    attn_kernel<<<TOKENS, 128>>>(query, kvproj, ctx);

    // out = ctx @ Wo^T           [32768,1024] x [1024,1024]^T
    sgemm_tn<<<dim3(DIM / BN, TOKENS / BM), 256>>>(ctx, Wo, out, TOKENS, DIM, DIM);
}

// round 3
// speedup vs baseline: 1.4189x; 1.4189x over previous
#include <cuda_runtime.h>
#include <cuda_bf16.h>
#include <math.h>
#include <stdint.h>

// ---------------------------------------------------------------------------
// Problem constants
// ---------------------------------------------------------------------------
#define TOKENS   32768      // 16 * 2048
#define DIM      1024
#define HEADS    8
#define DHEAD    128
#define LN_EPS   1e-5f

// GEMM tiling (mma.sync bf16 path)
#define BM       128
#define BN       128
#define BK       64          // bf16 elems per K-chunk
#define NCHUNK   48          // 3 split terms * (1024/64)
#define SA       144         // smem row stride bytes (64*2 + 16 pad) -> conflict-free ldmatrix
#define TILEB    (128 * SA)  // 18432 bytes per tile (A or B)
#define BUFB     (2 * TILEB) // 36864 per stage (A+B)
#define SMEMB    (2 * BUFB)  // 73728 double-buffered

// ---------------------------------------------------------------------------
// Scratch (device globals; cudaMalloc forbidden)
// ---------------------------------------------------------------------------
__device__ __nv_bfloat16 g_qn_hi [TOKENS * DIM];
__device__ __nv_bfloat16 g_qn_lo [TOKENS * DIM];
__device__ __nv_bfloat16 g_kvn_hi[TOKENS * DIM];
__device__ __nv_bfloat16 g_kvn_lo[TOKENS * DIM];
__device__ __nv_bfloat16 g_wq_hi [DIM * DIM];
__device__ __nv_bfloat16 g_wq_lo [DIM * DIM];
__device__ __nv_bfloat16 g_wkv_hi[2 * DIM * DIM];
__device__ __nv_bfloat16 g_wkv_lo[2 * DIM * DIM];
__device__ __nv_bfloat16 g_wo_hi [DIM * DIM];
__device__ __nv_bfloat16 g_wo_lo [DIM * DIM];
__device__ float         g_query [TOKENS * DIM];
__device__ float         g_kvproj[TOKENS * 2 * DIM];
__device__ __nv_bfloat16 g_ctx_hi[TOKENS * DIM];
__device__ __nv_bfloat16 g_ctx_lo[TOKENS * DIM];

// ---------------------------------------------------------------------------
// PTX helpers (all plain sm_80/sm_90-level features; no 'a' target needed)
// ---------------------------------------------------------------------------
__device__ __forceinline__ uint32_t smem_u32(const void* p) {
    uint32_t a;
    asm("{ .reg .u64 t; cvta.to.shared.u64 t, %1; cvt.u32.u64 %0, t; }" : "=r"(a) : "l"(p));
    return a;
}

__device__ __forceinline__ void cp16(uint32_t dst, const void* src) {
    asm volatile("cp.async.cg.shared.global [%0], [%1], 16;" :: "r"(dst), "l"(src));
}
#define CP_COMMIT() asm volatile("cp.async.commit_group;" ::: "memory")
#define CP_WAIT0()  asm volatile("cp.async.wait_group 0;" ::: "memory")

__device__ __forceinline__ void ldsm4(uint32_t* r, uint32_t addr) {
    asm volatile("ldmatrix.sync.aligned.m8n8.x4.shared.b16 {%0,%1,%2,%3}, [%4];"
                 : "=r"(r[0]), "=r"(r[1]), "=r"(r[2]), "=r"(r[3]) : "r"(addr));
}

__device__ __forceinline__ void mma16816(float* d, const uint32_t* a, uint32_t b0, uint32_t b1) {
    asm volatile("mma.sync.aligned.m16n8k16.row.col.f32.bf16.bf16.f32 "
                 "{%0,%1,%2,%3}, {%4,%5,%6,%7}, {%8,%9}, {%0,%1,%2,%3};"
                 : "+f"(d[0]), "+f"(d[1]), "+f"(d[2]), "+f"(d[3])
                 : "r"(a[0]), "r"(a[1]), "r"(a[2]), "r"(a[3]), "r"(b0), "r"(b1));
}

// ---------------------------------------------------------------------------
// LayerNorm + bf16 hi/lo split.  One block per row, 256 threads, float4/thread.
// ---------------------------------------------------------------------------
__global__ __launch_bounds__(256)
void ln_split_kernel(const float* __restrict__ x,
                     const float* __restrict__ gamma,
                     const float* __restrict__ beta,
                     __nv_bfloat16* __restrict__ hi,
                     __nv_bfloat16* __restrict__ lo) {
    const int row = blockIdx.x;
    const int tid = threadIdx.x;
    float4 v = ((const float4*)(x + (size_t)row * DIM))[tid];

    float s  = v.x + v.y + v.z + v.w;
    float sq = v.x * v.x + v.y * v.y + v.z * v.z + v.w * v.w;
    #pragma unroll
    for (int o = 16; o > 0; o >>= 1) {
        s  += __shfl_xor_sync(0xffffffffu, s,  o);
        sq += __shfl_xor_sync(0xffffffffu, sq, o);
    }
    __shared__ float rs[8], rq[8];
    const int wid = tid >> 5, lane = tid & 31;
    if (lane == 0) { rs[wid] = s; rq[wid] = sq; }
    __syncthreads();
    float tot = 0.f, totq = 0.f;
    #pragma unroll
    for (int i = 0; i < 8; i++) { tot += rs[i]; totq += rq[i]; }

    const float mu   = tot * (1.0f / DIM);
    const float var  = totq * (1.0f / DIM) - mu * mu;
    const float rinv = rsqrtf(var + LN_EPS);

    float4 g = ((const float4*)gamma)[tid];
    float4 b = ((const float4*)beta)[tid];
    float o0 = (v.x - mu) * rinv * g.x + b.x;
    float o1 = (v.y - mu) * rinv * g.y + b.y;
    float o2 = (v.z - mu) * rinv * g.z + b.z;
    float o3 = (v.w - mu) * rinv * g.w + b.w;

    __nv_bfloat16 h0 = __float2bfloat16_rn(o0), h1 = __float2bfloat16_rn(o1);
    __nv_bfloat16 h2 = __float2bfloat16_rn(o2), h3 = __float2bfloat16_rn(o3);
    __nv_bfloat16 l0 = __float2bfloat16_rn(o0 - __bfloat162float(h0));
    __nv_bfloat16 l1 = __float2bfloat16_rn(o1 - __bfloat162float(h1));
    __nv_bfloat16 l2 = __float2bfloat16_rn(o2 - __bfloat162float(h2));
    __nv_bfloat16 l3 = __float2bfloat16_rn(o3 - __bfloat162float(h3));

    __nv_bfloat162* hp = (__nv_bfloat162*)(hi + (size_t)row * DIM);
    __nv_bfloat162* lp = (__nv_bfloat162*)(lo + (size_t)row * DIM);
    hp[2 * tid]     = __halves2bfloat162(h0, h1);
    hp[2 * tid + 1] = __halves2bfloat162(h2, h3);
    lp[2 * tid]     = __halves2bfloat162(l0, l1);
    lp[2 * tid + 1] = __halves2bfloat162(l2, l3);
}

// ---------------------------------------------------------------------------
// Weight split (elementwise)
// ---------------------------------------------------------------------------
__global__ __launch_bounds__(256)
void wsplit_kernel(const float* __restrict__ w,
                   __nv_bfloat16* __restrict__ hi,
                   __nv_bfloat16* __restrict__ lo, int n) {
    int i = blockIdx.x * 256 + threadIdx.x;
    if (i < n) {
        float x = w[i];
        __nv_bfloat16 h = __float2bfloat16_rn(x);
        hi[i] = h;
        lo[i] = __float2bfloat16_rn(x - __bfloat162float(h));
    }
}

// ---------------------------------------------------------------------------
// Split-3 bf16 GEMM via mma.sync:  C[M,N] = A[M,K]*B[N,K]^T, fp32 accum.
// Streams 48 K-chunks: t=0:(hi,hi)  t=1:(lo,hi)  t=2:(hi,lo)
// 256 threads, warp grid 2(m) x 4(n), warp tile 64x32, cp.async double buffer.
// ---------------------------------------------------------------------------
__global__ __launch_bounds__(256, 1)
void gemm_mma_split(const __nv_bfloat16* __restrict__ Ah, const __nv_bfloat16* __restrict__ Al,
                    const __nv_bfloat16* __restrict__ Bh, const __nv_bfloat16* __restrict__ Bl,
                    float* __restrict__ C, int ldc) {
    extern __shared__ char smem[];
    const uint32_t sbase = smem_u32(smem);
    const int tid  = threadIdx.x;
    const int wid  = tid >> 5;
    const int lane = tid & 31;
    const int bm = blockIdx.y * BM;
    const int bn = blockIdx.x * BN;
    const int m_base = (wid >> 2) * 64;   // 0 or 64
    const int n_base = (wid & 3) * 32;    // 0,32,64,96

    float acc[4][4][4];
    #pragma unroll
    for (int i = 0; i < 4; i++)
        #pragma unroll
        for (int j = 0; j < 4; j++)
            #pragma unroll
            for (int k = 0; k < 4; k++) acc[i][j][k] = 0.f;

    const int lrow = lane & 15;
    const int lsel = (lane >> 4) * 16;    // 0 or 16 bytes

    // ---- tile loader: 128 rows x 128B for A and B, 16B per cp.async ----
    auto load_tile = [&](int c, int buf) {
        const int kk = c / 3;
        const int t  = c - 3 * kk;
        const __nv_bfloat16* As = (t == 1) ? Al : Ah;
        const __nv_bfloat16* Bs = (t == 2) ? Bl : Bh;
        const uint32_t ab = sbase + buf * BUFB;
        const uint32_t bb = ab + TILEB;
        #pragma unroll
        for (int i = 0; i < 4; i++) {
            const int idx = tid + i * 256;
            const int row = idx >> 3;
            const int c8  = idx & 7;
            cp16(ab + row * SA + c8 * 16, As + (size_t)(bm + row) * DIM + kk * BK + c8 * 8);
            cp16(bb + row * SA + c8 * 16, Bs + (size_t)(bn + row) * DIM + kk * BK + c8 * 8);
        }
        CP_COMMIT();
    };

    load_tile(0, 0);

    for (int c = 0; c < NCHUNK; c++) {
        const int buf = c & 1;
        CP_WAIT0();
        __syncthreads();
        if (c + 1 < NCHUNK) load_tile(c + 1, buf ^ 1);

        const uint32_t ab = sbase + buf * BUFB;
        const uint32_t bb = ab + TILEB;
        const uint32_t aaddr = ab + (m_base + lrow) * SA + lsel;
        const uint32_t baddr = bb + (n_base + lrow) * SA + lsel;

        #pragma unroll
        for (int ks = 0; ks < 4; ks++) {
            uint32_t ar[4][4], br[2][4];
            #pragma unroll
            for (int mi = 0; mi < 4; mi++) ldsm4(ar[mi], aaddr + mi * 16 * SA + ks * 32);
            #pragma unroll
            for (int ni = 0; ni < 2; ni++) ldsm4(br[ni], baddr + ni * 16 * SA + ks * 32);
            #pragma unroll
            for (int mi = 0; mi < 4; mi++)
                #pragma unroll
                for (int nj = 0; nj < 4; nj++)
                    mma16816(acc[mi][nj], ar[mi],
                             br[nj >> 1][nj & 1], br[nj >> 1][2 + (nj & 1)]);
        }
    }

    // ---- epilogue: fp32 C stores (float2 per fragment half) ----
    const int g  = lane >> 2;
    const int t2 = (lane & 3) * 2;
    #pragma unroll
    for (int mi = 0; mi < 4; mi++) {
        const int row = bm + m_base + mi * 16 + g;
        float* crow = C + (size_t)row * ldc + bn + n_base + t2;
        #pragma unroll
        for (int nj = 0; nj < 4; nj++) {
            *(float2*)(crow + nj * 8)             = make_float2(acc[mi][nj][0], acc[mi][nj][1]);
            *(float2*)(crow + (size_t)8 * ldc + nj * 8) = make_float2(acc[mi][nj][2], acc[mi][nj][3]);
        }
    }
}

// ---------------------------------------------------------------------------
// Per-token attention over HEADS axis; emits split-bf16 context.
// ---------------------------------------------------------------------------
__global__ __launch_bounds__(128)
void attn_kernel(const float* __restrict__ query,
                 const float* __restrict__ kvproj,
                 __nv_bfloat16* __restrict__ ctx_hi,
                 __nv_bfloat16* __restrict__ ctx_lo) {
    const int t = blockIdx.x;
    const int tid = threadIdx.x;
    __shared__ float qs[DIM], ks[DIM], vs[DIM];
    __shared__ float w[HEADS * HEADS];
    __shared__ float sc[HEADS * HEADS];

    const float4* qp = (const float4*)(query + (size_t)t * DIM);
    const float4* kp = (const float4*)(kvproj + (size_t)t * 2 * DIM);
    const float4* vp = kp + DIM / 4;
    ((float4*)qs)[tid]       = qp[tid];
    ((float4*)qs)[tid + 128] = qp[tid + 128];
    ((float4*)ks)[tid]       = kp[tid];
    ((float4*)ks)[tid + 128] = kp[tid + 128];
    ((float4*)vs)[tid]       = vp[tid];
    ((float4*)vs)[tid + 128] = vp[tid + 128];
    __syncthreads();

    if (tid < HEADS * HEADS) {
        const int h = tid >> 3, g = tid & 7;
        const float* qq = qs + h * DHEAD;
        const float* kk = ks + g * DHEAD;
        float s = 0.f;
        #pragma unroll 8
        for (int d = 0; d < DHEAD; d++) s += qq[d] * kk[d];
        sc[tid] = s * 0.08838834764831845f;   // 1/sqrt(128)
    }
    __syncthreads();

    if (tid < HEADS) {
        float m = -1e30f;
        #pragma unroll
        for (int g = 0; g < HEADS; g++) m = fmaxf(m, sc[tid * 8 + g]);
        float e[HEADS], sum = 0.f;
        #pragma unroll
        for (int g = 0; g < HEADS; g++) { e[g] = expf(sc[tid * 8 + g] - m); sum += e[g]; }
        const float inv = 1.0f / sum;
        #pragma unroll
        for (int g = 0; g < HEADS; g++) w[tid * 8 + g] = e[g] * inv;
    }
    __syncthreads();

    #pragma unroll
    for (int h = 0; h < HEADS; h++) {
        float a = 0.f;
        #pragma unroll
        for (int g = 0; g < HEADS; g++) a += w[h * 8 + g] * vs[g * DHEAD + tid];
        const size_t idx = (size_t)t * DIM + h * DHEAD + tid;
        __nv_bfloat16 hval = __float2bfloat16_rn(a);
        ctx_hi[idx] = hval;
        ctx_lo[idx] = __float2bfloat16_rn(a - __bfloat162float(hval));
    }
}

// ---------------------------------------------------------------------------
// Host side
// ---------------------------------------------------------------------------
extern "C" void kernel_launch(void* const* d_in, const int* in_sizes, int n_in,
                              void* d_out, int out_size) {
    const float* q       = (const float*)d_in[0];
    const float* kv      = (const float*)d_in[1];
    const float* gamma_m = (const float*)d_in[2];
    const float* beta_m  = (const float*)d_in[3];
    const float* gamma_l = (const float*)d_in[4];
    const float* beta_l  = (const float*)d_in[5];
    const float* Wq      = (const float*)d_in[6];
    const float* Wkv     = (const float*)d_in[7];
    const float* Wo      = (const float*)d_in[8];
    float* out = (float*)d_out;

    void *qn_hi, *qn_lo, *kvn_hi, *kvn_lo, *wq_hi, *wq_lo, *wkv_hi, *wkv_lo, *wo_hi, *wo_lo;
    void *query, *kvproj, *ctx_hi, *ctx_lo;
    cudaGetSymbolAddress(&qn_hi,  g_qn_hi);   cudaGetSymbolAddress(&qn_lo,  g_qn_lo);
    cudaGetSymbolAddress(&kvn_hi, g_kvn_hi);  cudaGetSymbolAddress(&kvn_lo, g_kvn_lo);
    cudaGetSymbolAddress(&wq_hi,  g_wq_hi);   cudaGetSymbolAddress(&wq_lo,  g_wq_lo);
    cudaGetSymbolAddress(&wkv_hi, g_wkv_hi);  cudaGetSymbolAddress(&wkv_lo, g_wkv_lo);
    cudaGetSymbolAddress(&wo_hi,  g_wo_hi);   cudaGetSymbolAddress(&wo_lo,  g_wo_lo);
    cudaGetSymbolAddress(&query,  g_query);   cudaGetSymbolAddress(&kvproj, g_kvproj);
    cudaGetSymbolAddress(&ctx_hi, g_ctx_hi);  cudaGetSymbolAddress(&ctx_lo, g_ctx_lo);

    cudaFuncSetAttribute(gemm_mma_split, cudaFuncAttributeMaxDynamicSharedMemorySize, SMEMB);

    // LN + split
    ln_split_kernel<<<TOKENS, 256>>>(q,  gamma_m, beta_m,
                                     (__nv_bfloat16*)qn_hi,  (__nv_bfloat16*)qn_lo);
    ln_split_kernel<<<TOKENS, 256>>>(kv, gamma_l, beta_l,
                                     (__nv_bfloat16*)kvn_hi, (__nv_bfloat16*)kvn_lo);
    // weight splits
    wsplit_kernel<<<(DIM*DIM + 255)/256, 256>>>(Wq,  (__nv_bfloat16*)wq_hi,  (__nv_bfloat16*)wq_lo,  DIM*DIM);
    wsplit_kernel<<<(2*DIM*DIM + 255)/256, 256>>>(Wkv, (__nv_bfloat16*)wkv_hi, (__nv_bfloat16*)wkv_lo, 2*DIM*DIM);
    wsplit_kernel<<<(DIM*DIM + 255)/256, 256>>>(Wo,  (__nv_bfloat16*)wo_hi,  (__nv_bfloat16*)wo_lo,  DIM*DIM);

    // GEMM1: query = qn @ Wq^T   [32768,1024]
    gemm_mma_split<<<dim3(DIM / BN, TOKENS / BM), 256, SMEMB>>>(
        (const __nv_bfloat16*)qn_hi, (const __nv_bfloat16*)qn_lo,
        (const __nv_bfloat16*)wq_hi, (const __nv_bfloat16*)wq_lo,
        (float*)query, DIM);
    // GEMM2: kvproj = kvn @ Wkv^T  [32768,2048]
    gemm_mma_split<<<dim3(2 * DIM / BN, TOKENS / BM), 256, SMEMB>>>(
        (const __nv_bfloat16*)kvn_hi, (const __nv_bfloat16*)kvn_lo,
        (const __nv_bfloat16*)wkv_hi, (const __nv_bfloat16*)wkv_lo,
        (float*)kvproj, 2 * DIM);

    attn_kernel<<<TOKENS, 128>>>((const float*)query, (const float*)kvproj,
                                 (__nv_bfloat16*)ctx_hi, (__nv_bfloat16*)ctx_lo);

    // GEMM3: out = ctx @ Wo^T   [32768,1024]
    gemm_mma_split<<<dim3(DIM / BN, TOKENS / BM), 256, SMEMB>>>(
        (const __nv_bfloat16*)ctx_hi, (const __nv_bfloat16*)ctx_lo,
        (const __nv_bfloat16*)wo_hi, (const __nv_bfloat16*)wo_lo,
        out, DIM);
}

// round 4
// speedup vs baseline: 3.2025x; 2.2570x over previous
#include <cuda_runtime.h>
#include <cuda_fp16.h>
#include <math.h>
#include <stdint.h>

// ---------------------------------------------------------------------------
// Problem constants
// ---------------------------------------------------------------------------
#define TOKENS   32768      // 16 * 2048
#define DIM      1024
#define HEADS    8
#define DHEAD    128
#define LN_EPS   1e-5f

// GEMM tiling: CTA 128x256, K-chunk 64, warp tile 64x64, 8 warps (2m x 4n)
#define BM       128
#define BN       256
#define BK       64
#define NKK      16           // 1024 / 64 K-chunks
#define STAGES   3
#define SA       144          // smem row stride (128B data + 16B pad), conflict-free ldmatrix
#define ROWS_PER_STAGE (BM + BM + BN)        // Ahi(128) + Alo(128) + B(256) = 512
#define STAGEB   (ROWS_PER_STAGE * SA)       // 73728
#define SMEMB    (STAGES * STAGEB)           // 221184  (< 232448 opt-in max)

// ---------------------------------------------------------------------------
// Scratch (device globals; cudaMalloc forbidden)
// ---------------------------------------------------------------------------
__device__ __half g_qn_hi [TOKENS * DIM];
__device__ __half g_qn_lo [TOKENS * DIM];
__device__ __half g_kvn_hi[TOKENS * DIM];
__device__ __half g_kvn_lo[TOKENS * DIM];
__device__ __half g_wq_h  [DIM * DIM];
__device__ __half g_wkv_h [2 * DIM * DIM];
__device__ __half g_wo_h  [DIM * DIM];
__device__ float  g_query [TOKENS * DIM];
__device__ float  g_kvproj[TOKENS * 2 * DIM];
__device__ __half g_ctx_hi[TOKENS * DIM];
__device__ __half g_ctx_lo[TOKENS * DIM];

// ---------------------------------------------------------------------------
// PTX helpers (plain sm_80-level; harness PTX target is sm_103 non-'a')
// ---------------------------------------------------------------------------
__device__ __forceinline__ uint32_t smem_u32(const void* p) {
    uint32_t a;
    asm("{ .reg .u64 t; cvta.to.shared.u64 t, %1; cvt.u32.u64 %0, t; }" : "=r"(a) : "l"(p));
    return a;
}

__device__ __forceinline__ void cp16(uint32_t dst, const void* src) {
    asm volatile("cp.async.cg.shared.global [%0], [%1], 16;" :: "r"(dst), "l"(src));
}
#define CP_COMMIT() asm volatile("cp.async.commit_group;" ::: "memory")
#define CP_WAIT1()  asm volatile("cp.async.wait_group 1;" ::: "memory")

__device__ __forceinline__ void ldsm4(uint32_t* r, uint32_t addr) {
    asm volatile("ldmatrix.sync.aligned.m8n8.x4.shared.b16 {%0,%1,%2,%3}, [%4];"
                 : "=r"(r[0]), "=r"(r[1]), "=r"(r[2]), "=r"(r[3]) : "r"(addr));
}

__device__ __forceinline__ void mma16816h(float* d, const uint32_t* a, uint32_t b0, uint32_t b1) {
    asm volatile("mma.sync.aligned.m16n8k16.row.col.f32.f16.f16.f32 "
                 "{%0,%1,%2,%3}, {%4,%5,%6,%7}, {%8,%9}, {%0,%1,%2,%3};"
                 : "+f"(d[0]), "+f"(d[1]), "+f"(d[2]), "+f"(d[3])
                 : "r"(a[0]), "r"(a[1]), "r"(a[2]), "r"(a[3]), "r"(b0), "r"(b1));
}

// ---------------------------------------------------------------------------
// LayerNorm + fp16 hi/lo split.  One block per row, 256 threads.
// ---------------------------------------------------------------------------
__global__ __launch_bounds__(256)
void ln_split_kernel(const float* __restrict__ x,
                     const float* __restrict__ gamma,
                     const float* __restrict__ beta,
                     __half* __restrict__ hi,
                     __half* __restrict__ lo) {
    const int row = blockIdx.x;
    const int tid = threadIdx.x;
    float4 v = ((const float4*)(x + (size_t)row * DIM))[tid];

    float s  = v.x + v.y + v.z + v.w;
    float sq = v.x * v.x + v.y * v.y + v.z * v.z + v.w * v.w;
    #pragma unroll
    for (int o = 16; o > 0; o >>= 1) {
        s  += __shfl_xor_sync(0xffffffffu, s,  o);
        sq += __shfl_xor_sync(0xffffffffu, sq, o);
    }
    __shared__ float rs[8], rq[8];
    const int wid = tid >> 5, lane = tid & 31;
    if (lane == 0) { rs[wid] = s; rq[wid] = sq; }
    __syncthreads();
    float tot = 0.f, totq = 0.f;
    #pragma unroll
    for (int i = 0; i < 8; i++) { tot += rs[i]; totq += rq[i]; }

    const float mu   = tot * (1.0f / DIM);
    const float var  = totq * (1.0f / DIM) - mu * mu;
    const float rinv = rsqrtf(var + LN_EPS);

    float4 g = ((const float4*)gamma)[tid];
    float4 b = ((const float4*)beta)[tid];
    float o0 = (v.x - mu) * rinv * g.x + b.x;
    float o1 = (v.y - mu) * rinv * g.y + b.y;
    float o2 = (v.z - mu) * rinv * g.z + b.z;
    float o3 = (v.w - mu) * rinv * g.w + b.w;

    __half h0 = __float2half_rn(o0), h1 = __float2half_rn(o1);
    __half h2 = __float2half_rn(o2), h3 = __float2half_rn(o3);
    __half l0 = __float2half_rn(o0 - __half2float(h0));
    __half l1 = __float2half_rn(o1 - __half2float(h1));
    __half l2 = __float2half_rn(o2 - __half2float(h2));
    __half l3 = __float2half_rn(o3 - __half2float(h3));

    __half2* hp = (__half2*)(hi + (size_t)row * DIM);
    __half2* lp = (__half2*)(lo + (size_t)row * DIM);
    hp[2 * tid]     = __halves2half2(h0, h1);
    hp[2 * tid + 1] = __halves2half2(h2, h3);
    lp[2 * tid]     = __halves2half2(l0, l1);
    lp[2 * tid + 1] = __halves2half2(l2, l3);
}

// ---------------------------------------------------------------------------
// Weight -> fp16 (single rounding; the only numeric loss in the scheme)
// ---------------------------------------------------------------------------
__global__ __launch_bounds__(256)
void whalf_kernel(const float* __restrict__ w, __half* __restrict__ h, int n) {
    int i = blockIdx.x * 256 + threadIdx.x;
    if (i < n) h[i] = __float2half_rn(w[i]);
}

// ---------------------------------------------------------------------------
// fp16 2-term GEMM:  C[M,N] = (Ahi + Alo)[M,K] * B[N,K]^T, fp32 accum.
// CTA 128x256, 8 warps of 64x64, 3-stage cp.async pipeline.
// Stage layout: [Ahi 128 rows][Alo 128 rows][B 256 rows], row = 128B + 16 pad.
// ---------------------------------------------------------------------------
__global__ __launch_bounds__(256, 1)
void gemm_fp16_2term(const __half* __restrict__ Ah, const __half* __restrict__ Al,
                     const __half* __restrict__ B, float* __restrict__ C, int ldc) {
    extern __shared__ char smem[];
    const uint32_t sbase = smem_u32(smem);
    const int tid  = threadIdx.x;
    const int wid  = tid >> 5;
    const int lane = tid & 31;
    const int bm = blockIdx.y * BM;
    const int bn = blockIdx.x * BN;
    const int m_base = (wid >> 2) * 64;   // 0 or 64
    const int n_base = (wid & 3) * 64;    // 0,64,128,192

    float acc[4][8][4];
    #pragma unroll
    for (int i = 0; i < 4; i++)
        #pragma unroll
        for (int j = 0; j < 8; j++)
            #pragma unroll
            for (int k = 0; k < 4; k++) acc[i][j][k] = 0.f;

    // stage loader: 512 rows x 128B, 16B per cp.async, 16 per thread
    auto load_stage = [&](int kk, int s) {
        const uint32_t st = sbase + s * STAGEB;
        #pragma unroll
        for (int i = 0; i < 16; i++) {
            const int idx = tid + i * 256;
            const int row = idx >> 3;          // 0..511
            const int c8  = idx & 7;
            const __half* src;
            if (row < 128)      src = Ah + (size_t)(bm + row) * DIM + kk * BK + c8 * 8;
            else if (row < 256) src = Al + (size_t)(bm + row - 128) * DIM + kk * BK + c8 * 8;
            else                src = B  + (size_t)(bn + row - 256) * DIM + kk * BK + c8 * 8;
            cp16(st + row * SA + c8 * 16, src);
        }
        CP_COMMIT();
    };

    load_stage(0, 0);
    load_stage(1, 1);

    const int lrow = lane & 15;
    const int lsel = (lane >> 4) * 16;    // 0 or 16 bytes

    for (int kk = 0; kk < NKK; kk++) {
        CP_WAIT1();                        // stage kk resident
        __syncthreads();
        if (kk + 2 < NKK) load_stage(kk + 2, (kk + 2) % STAGES);
        else              CP_COMMIT();     // empty group keeps wait_group 1 sound

        const uint32_t st     = sbase + (kk % STAGES) * STAGEB;
        const uint32_t ahaddr = st + (m_base + lrow) * SA + lsel;
        const uint32_t aladdr = ahaddr + 128 * SA;
        const uint32_t baddr  = st + 256 * SA + (n_base + lrow) * SA + lsel;

        #pragma unroll
        for (int ks = 0; ks < 4; ks++) {
            uint32_t br[4][4];
            #pragma unroll
            for (int ni = 0; ni < 4; ni++) ldsm4(br[ni], baddr + ni * 16 * SA + ks * 32);

            uint32_t ar[4][4];
            #pragma unroll
            for (int mi = 0; mi < 4; mi++) ldsm4(ar[mi], ahaddr + mi * 16 * SA + ks * 32);
            #pragma unroll
            for (int mi = 0; mi < 4; mi++)
                #pragma unroll
                for (int nj = 0; nj < 8; nj++)
                    mma16816h(acc[mi][nj], ar[mi],
                              br[nj >> 1][nj & 1], br[nj >> 1][2 + (nj & 1)]);

            #pragma unroll
            for (int mi = 0; mi < 4; mi++) ldsm4(ar[mi], aladdr + mi * 16 * SA + ks * 32);
            #pragma unroll
            for (int mi = 0; mi < 4; mi++)
                #pragma unroll
                for (int nj = 0; nj < 8; nj++)
                    mma16816h(acc[mi][nj], ar[mi],
                              br[nj >> 1][nj & 1], br[nj >> 1][2 + (nj & 1)]);
        }
    }

    // epilogue: fp32 C stores
    const int g  = lane >> 2;
    const int t2 = (lane & 3) * 2;
    #pragma unroll
    for (int mi = 0; mi < 4; mi++) {
        const int row = bm + m_base + mi * 16 + g;
        float* crow = C + (size_t)row * ldc + bn + n_base + t2;
        #pragma unroll
        for (int nj = 0; nj < 8; nj++) {
            *(float2*)(crow + nj * 8)                   = make_float2(acc[mi][nj][0], acc[mi][nj][1]);
            *(float2*)(crow + (size_t)8 * ldc + nj * 8) = make_float2(acc[mi][nj][2], acc[mi][nj][3]);
        }
    }
}

// ---------------------------------------------------------------------------
// Per-token attention over HEADS axis; emits split-fp16 context.
// ---------------------------------------------------------------------------
__global__ __launch_bounds__(128)
void attn_kernel(const float* __restrict__ query,
                 const float* __restrict__ kvproj,
                 __half* __restrict__ ctx_hi,
                 __half* __restrict__ ctx_lo) {
    const int t = blockIdx.x;
    const int tid = threadIdx.x;
    __shared__ float qs[DIM], ks[DIM], vs[DIM];
    __shared__ float w[HEADS * HEADS];
    __shared__ float sc[HEADS * HEADS];

    const float4* qp = (const float4*)(query + (size_t)t * DIM);
    const float4* kp = (const float4*)(kvproj + (size_t)t * 2 * DIM);
    const float4* vp = kp + DIM / 4;
    ((float4*)qs)[tid]       = qp[tid];
    ((float4*)qs)[tid + 128] = qp[tid + 128];
    ((float4*)ks)[tid]       = kp[tid];
    ((float4*)ks)[tid + 128] = kp[tid + 128];
    ((float4*)vs)[tid]       = vp[tid];
    ((float4*)vs)[tid + 128] = vp[tid + 128];
    __syncthreads();

    if (tid < HEADS * HEADS) {
        const int h = tid >> 3, g = tid & 7;
        const float* qq = qs + h * DHEAD;
        const float* kk = ks + g * DHEAD;
        float s = 0.f;
        #pragma unroll 8
        for (int d = 0; d < DHEAD; d++) s += qq[d] * kk[d];
        sc[tid] = s * 0.08838834764831845f;   // 1/sqrt(128)
    }
    __syncthreads();

    if (tid < HEADS) {
        float m = -1e30f;
        #pragma unroll
        for (int g = 0; g < HEADS; g++) m = fmaxf(m, sc[tid * 8 + g]);
        float e[HEADS], sum = 0.f;
        #pragma unroll
        for (int g = 0; g < HEADS; g++) { e[g] = expf(sc[tid * 8 + g] - m); sum += e[g]; }
        const float inv = 1.0f / sum;
        #pragma unroll
        for (int g = 0; g < HEADS; g++) w[tid * 8 + g] = e[g] * inv;
    }
    __syncthreads();

    #pragma unroll
    for (int h = 0; h < HEADS; h++) {
        float a = 0.f;
        #pragma unroll
        for (int g = 0; g < HEADS; g++) a += w[h * 8 + g] * vs[g * DHEAD + tid];
        const size_t idx = (size_t)t * DIM + h * DHEAD + tid;
        __half hv = __float2half_rn(a);
        ctx_hi[idx] = hv;
        ctx_lo[idx] = __float2half_rn(a - __half2float(hv));
    }
}

// ---------------------------------------------------------------------------
// Host side
// ---------------------------------------------------------------------------
extern "C" void kernel_launch(void* const* d_in, const int* in_sizes, int n_in,
                              void* d_out, int out_size) {
    const float* q       = (const float*)d_in[0];
    const float* kv      = (const float*)d_in[1];
    const float* gamma_m = (const float*)d_in[2];
    const float* beta_m  = (const float*)d_in[3];
    const float* gamma_l = (const float*)d_in[4];
    const float* beta_l  = (const float*)d_in[5];
    const float* Wq      = (const float*)d_in[6];
    const float* Wkv     = (const float*)d_in[7];
    const float* Wo      = (const float*)d_in[8];
    float* out = (float*)d_out;

    void *qn_hi, *qn_lo, *kvn_hi, *kvn_lo, *wq_h, *wkv_h, *wo_h;
    void *query, *kvproj, *ctx_hi, *ctx_lo;
    cudaGetSymbolAddress(&qn_hi,  g_qn_hi);   cudaGetSymbolAddress(&qn_lo,  g_qn_lo);
    cudaGetSymbolAddress(&kvn_hi, g_kvn_hi);  cudaGetSymbolAddress(&kvn_lo, g_kvn_lo);
    cudaGetSymbolAddress(&wq_h,   g_wq_h);    cudaGetSymbolAddress(&wkv_h,  g_wkv_h);
    cudaGetSymbolAddress(&wo_h,   g_wo_h);
    cudaGetSymbolAddress(&query,  g_query);   cudaGetSymbolAddress(&kvproj, g_kvproj);
    cudaGetSymbolAddress(&ctx_hi, g_ctx_hi);  cudaGetSymbolAddress(&ctx_lo, g_ctx_lo);

    cudaFuncSetAttribute(gemm_fp16_2term, cudaFuncAttributeMaxDynamicSharedMemorySize, SMEMB);

    // LN + split (activations), weights -> fp16
    ln_split_kernel<<<TOKENS, 256>>>(q,  gamma_m, beta_m, (__half*)qn_hi,  (__half*)qn_lo);
    ln_split_kernel<<<TOKENS, 256>>>(kv, gamma_l, beta_l, (__half*)kvn_hi, (__half*)kvn_lo);
    whalf_kernel<<<(DIM*DIM + 255)/256, 256>>>(Wq,  (__half*)wq_h,  DIM*DIM);
    whalf_kernel<<<(2*DIM*DIM + 255)/256, 256>>>(Wkv, (__half*)wkv_h, 2*DIM*DIM);
    whalf_kernel<<<(DIM*DIM + 255)/256, 256>>>(Wo,  (__half*)wo_h,  DIM*DIM);

    // GEMM1: query = qn @ Wq^T     [32768,1024]
    gemm_fp16_2term<<<dim3(DIM / BN, TOKENS / BM), 256, SMEMB>>>(
        (const __half*)qn_hi, (const __half*)qn_lo, (const __half*)wq_h,
        (float*)query, DIM);
    // GEMM2: kvproj = kvn @ Wkv^T  [32768,2048]
    gemm_fp16_2term<<<dim3(2 * DIM / BN, TOKENS / BM), 256, SMEMB>>>(
        (const __half*)kvn_hi, (const __half*)kvn_lo, (const __half*)wkv_h,
        (float*)kvproj, 2 * DIM);

    attn_kernel<<<TOKENS, 128>>>((const float*)query, (const float*)kvproj,
                                 (__half*)ctx_hi, (__half*)ctx_lo);

    // GEMM3: out = ctx @ Wo^T      [32768,1024]
    gemm_fp16_2term<<<dim3(DIM / BN, TOKENS / BM), 256, SMEMB>>>(
        (const __half*)ctx_hi, (const __half*)ctx_lo, (const __half*)wo_h,
        out, DIM);
}